// round 13
// baseline (speedup 1.0000x reference)
#include <cuda_runtime.h>
#include <cstdint>
#include <cstddef>

#define NN   1024
#define DIMX 384
#define HN   8
#define PDW  128
#define OUTW 1152   // H*DV + H*PD = 128 + 1024

static constexpr float SCALAR_SCALE = 0.14433756729740643f; // (3*16)^-0.5
static constexpr float PAIR_SCALE   = 0.5773502691896258f;  // 3^-0.5

// Scratch (static __device__ — no allocations allowed)
static __device__ float g_q[NN * 128];
static __device__ float g_k[NN * 128];
static __device__ float g_v[NN * 128];

typedef unsigned long long u64;

__device__ __forceinline__ u64 pack2(float lo, float hi) {
    u64 r; asm("mov.b64 %0, {%1, %2};" : "=l"(r) : "f"(lo), "f"(hi)); return r;
}
__device__ __forceinline__ void unpack2(u64 v, float& lo, float& hi) {
    asm("mov.b64 {%0, %1}, %2;" : "=f"(lo), "=f"(hi) : "l"(v));
}
__device__ __forceinline__ u64 ffma2(u64 a, u64 b, u64 c) {
    u64 r; asm("fma.rn.f32x2 %0, %1, %2, %3;" : "=l"(r) : "l"(a), "l"(b), "l"(c)); return r;
}
__device__ __forceinline__ uint32_t smem_u32(const void* p) {
    return (uint32_t)__cvta_generic_to_shared(p);
}
__device__ __forceinline__ void cp16_cg(uint32_t dst, const void* src) {
    asm volatile("cp.async.cg.shared.global [%0], [%1], 16;" :: "r"(dst), "l"(src));
}
__device__ __forceinline__ void cp16_ca(uint32_t dst, const void* src) {
    asm volatile("cp.async.ca.shared.global [%0], [%1], 16;" :: "r"(dst), "l"(src));
}
#define CP_COMMIT() asm volatile("cp.async.commit_group;" ::: "memory")
#define CP_WAIT(N)  asm volatile("cp.async.wait_group %0;" :: "n"(N) : "memory")

// smem layout constants (bytes)
#define STAGE_B   1536               // 512 pr + 512 k + 512 v
#define RING_WB   (4 * STAGE_B)      // 4 slots per warp = 6144
#define RING_B    (8 * RING_WB)      // 8 warps = 49152
#define MB_FLOATS (8 * 1160)
#define SMEM_B    (RING_B + MB_FLOATS * 4 + 32)   // 86464

// ---------------------------------------------------------------------------
// Kernel A: q/k/v projections. grid (64, 3), block 256 (8 warps).
// Warp = 8 rows x 32 cols: W slice/warp = 49 KB -> total W L2 traffic 75 MB.
// ---------------------------------------------------------------------------
__global__ void __launch_bounds__(256) proj_kernel(
    const float* __restrict__ x,
    const float* __restrict__ Wq,
    const float* __restrict__ Wk,
    const float* __restrict__ Wv)
{
    __shared__ float xs[16 * DIMX];   // 24 KB
    const int rb = blockIdx.x * 16;
    const float* W   = (blockIdx.y == 0) ? Wq  : (blockIdx.y == 1) ? Wk  : Wv;
    float*       dst = (blockIdx.y == 0) ? g_q : (blockIdx.y == 1) ? g_k : g_v;
    const float scale = (blockIdx.y == 0) ? SCALAR_SCALE : 1.0f;

    for (int t = threadIdx.x; t < 16 * DIMX; t += 256)
        xs[t] = x[(size_t)rb * DIMX + t];
    __syncthreads();

    const int wid  = threadIdx.x >> 5;
    const int lane = threadIdx.x & 31;
    const int rg   = wid >> 2;
    const int cg   = wid & 3;
    const int c    = cg * 32 + lane;
    const int r0   = rg * 8;

    float acc[8];
#pragma unroll
    for (int r = 0; r < 8; r++) acc[r] = 0.0f;

    float wbuf[4];
#pragma unroll
    for (int u = 0; u < 4; u++)
        wbuf[u] = __ldg(&W[u * 128 + c]);

#pragma unroll 1
    for (int k0 = 0; k0 < DIMX; k0 += 4) {
        float wcur[4];
#pragma unroll
        for (int u = 0; u < 4; u++) wcur[u] = wbuf[u];
        const int kn = (k0 + 4 < DIMX) ? (k0 + 4) : 0;   // clamp: valid addr
#pragma unroll
        for (int u = 0; u < 4; u++)
            wbuf[u] = __ldg(&W[(kn + u) * 128 + c]);
#pragma unroll
        for (int u = 0; u < 4; u++) {
#pragma unroll
            for (int r = 0; r < 8; r++)
                acc[r] = fmaf(xs[(r0 + r) * DIMX + k0 + u], wcur[u], acc[r]);
        }
    }
#pragma unroll
    for (int r = 0; r < 8; r++)
        dst[(size_t)(rb + r0 + r) * 128 + c] = acc[r] * scale;
}

// ---------------------------------------------------------------------------
// Kernel B: FULLY FUSED single pass, cp.async-staged. grid 1024 (CTA = i),
// block 256 (8 warps; warp = 128 consecutive j). 2 CTAs/SM -> 16 warps/SM.
// Lane = (h = lane&7, q = lane>>3).
// Per j: 3 cp.async (pr .cg, k/v .ca) fill a 4-slot smem ring (zero regs);
// wait_group 2 keeps 3 rows (4.5 KB/warp) in flight. Consumer: LDS pr chunks
// (u*4+q), lane-local bias-dot + qk-dot, xor8/16 fold, exp, accp (pr re-read
// from smem after exp to cap transient regs), accv, l. ~105 regs -> no spill.
// Epilogue: smem reduce across 8 warps, normalize, direct store.
// ---------------------------------------------------------------------------
__global__ void __launch_bounds__(256, 2) fused_kernel(
    const float* __restrict__ pair,
    const float* __restrict__ Wb,
    const float* __restrict__ bb,
    float* __restrict__ out)
{
    extern __shared__ char smem[];
    float* mb = (float*)(smem + RING_B);             // 8 x 1160 partials
    float* rs = (float*)(smem + RING_B + MB_FLOATS * 4);

    const int tid  = threadIdx.x;
    const int wid  = tid >> 5;
    const int lane = tid & 31;
    const int h    = lane & 7;
    const int q    = lane >> 3;

    const int i  = blockIdx.x;
    const int j0 = wid * 128;

    // Wb rows for this lane's d-set (chunks f = u*4+q), pre-scaled.
    u64 wb2[16];
#pragma unroll
    for (int u = 0; u < 8; u++) {
        const int d = (u * 4 + q) * 4;
        wb2[2 * u]     = pack2(Wb[(d + 0) * 8 + h] * PAIR_SCALE, Wb[(d + 1) * 8 + h] * PAIR_SCALE);
        wb2[2 * u + 1] = pack2(Wb[(d + 2) * 8 + h] * PAIR_SCALE, Wb[(d + 3) * 8 + h] * PAIR_SCALE);
    }
    const float4 qv = *(const float4*)&g_q[(size_t)i * 128 + h * 16 + q * 4];
    const float bbh = bb[h] * PAIR_SCALE;
    const int koff = h * 4 + q;          // float4 index of (h,q) slice in a row

    // byte sources for this warp's j-range
    const char* prsrc = (const char*)pair + ((size_t)i * NN + j0) * 512;
    const char* ksrc  = (const char*)g_k + (size_t)j0 * 512;
    const char* vsrc  = (const char*)g_v + (size_t)j0 * 512;
    const int lb = lane * 16;

    const uint32_t ringw = smem_u32(smem) + wid * RING_WB;
    char* ringp = smem + wid * RING_WB;

    u64 accp[16];
#pragma unroll
    for (int t = 0; t < 16; t++) accp[t] = 0ull;
    float4 accv = make_float4(0.f, 0.f, 0.f, 0.f);
    float l = 0.0f;

    // prologue: stage rows 0,1,2 (3 groups)
#pragma unroll
    for (int t = 0; t < 3; t++) {
        const uint32_t s = ringw + t * STAGE_B;
        cp16_cg(s +        lb, prsrc + (size_t)t * 512 + lb);
        cp16_ca(s +  512 + lb, ksrc  + (size_t)t * 512 + lb);
        cp16_ca(s + 1024 + lb, vsrc  + (size_t)t * 512 + lb);
        CP_COMMIT();
    }

#pragma unroll 1
    for (int t = 0; t < 128; t++) {
        CP_WAIT(2);                      // rows up to t complete (2 newer pend)
        __syncwarp();

        const float4* sp = (const float4*)(ringp + (t & 3) * STAGE_B);

        // bias dot over own (h, d-chunks u*4+q)
        u64 a0 = 0ull, a1 = 0ull;
#pragma unroll
        for (int u = 0; u < 8; u++) {
            const float4 c = sp[u * 4 + q];
            a0 = ffma2(pack2(c.x, c.y), wb2[2 * u],     a0);
            a1 = ffma2(pack2(c.z, c.w), wb2[2 * u + 1], a1);
        }
        const float4 kc = sp[32 + koff];         // k row at byte 512
        const float4 vc = sp[64 + koff];         // v row at byte 1024

        float d0, d1, d2, d3;
        unpack2(a0, d0, d1); unpack2(a1, d2, d3);
        float qk = qv.x * kc.x;
        qk = fmaf(qv.y, kc.y, qk);
        qk = fmaf(qv.z, kc.z, qk);
        qk = fmaf(qv.w, kc.w, qk);

        float dot = ((d0 + d1) + (d2 + d3)) + qk;
        dot += __shfl_xor_sync(0xffffffffu, dot, 8);
        dot += __shfl_xor_sync(0xffffffffu, dot, 16);

        const float p = __expf(dot + bbh);       // same on all 4 q-lanes of h
        l += p;
        const u64 ph = pack2(p, p);

        // accp: re-read pr chunks from smem (caps transient registers)
#pragma unroll
        for (int u = 0; u < 8; u++) {
            const float4 c = sp[u * 4 + q];
            accp[2 * u]     = ffma2(ph, pack2(c.x, c.y), accp[2 * u]);
            accp[2 * u + 1] = ffma2(ph, pack2(c.z, c.w), accp[2 * u + 1]);
        }
        accv.x = fmaf(p, vc.x, accv.x);
        accv.y = fmaf(p, vc.y, accv.y);
        accv.z = fmaf(p, vc.z, accv.z);
        accv.w = fmaf(p, vc.w, accv.w);

        __syncwarp();                    // all lanes done reading slot before refill

        // refill: row (t+3) (wrapped; slot (t+3)&3 is free)
        const int tr = (t + 3) & 127;
        const uint32_t s = ringw + ((t + 3) & 3) * STAGE_B;
        cp16_cg(s +        lb, prsrc + (size_t)tr * 512 + lb);
        cp16_ca(s +  512 + lb, ksrc  + (size_t)tr * 512 + lb);
        cp16_ca(s + 1024 + lb, vsrc  + (size_t)tr * 512 + lb);
        CP_COMMIT();
    }
    CP_WAIT(0);

    // ---- epilogue: dump per-warp partials, reduce across 8 warps ----
    {
        float* m = mb + wid * 1160;
        *(float4*)&m[koff * 4] = accv;                    // v part: h*16 + q*4
#pragma unroll
        for (int u = 0; u < 8; u++) {
            float a0, a1, a2, a3;
            unpack2(accp[2 * u],     a0, a1);
            unpack2(accp[2 * u + 1], a2, a3);
            *(float4*)&m[128 + h * 128 + u * 16 + q * 4] = make_float4(a0, a1, a2, a3);
        }
        if (q == 0) m[1152 + h] = l;
    }
    __syncthreads();

    if (tid < 8) {
        float s = 0.0f;
#pragma unroll
        for (int w = 0; w < 8; w++) s += mb[w * 1160 + 1152 + tid];
        rs[tid] = 1.0f / s;
    }
    __syncthreads();

    const size_t ob = (size_t)i * OUTW;
    for (int idx = tid; idx < OUTW; idx += 256) {
        float s = 0.0f;
#pragma unroll
        for (int w = 0; w < 8; w++) s += mb[w * 1160 + idx];
        const int head = (idx < 128) ? (idx >> 4) : ((idx - 128) >> 7);
        out[ob + idx] = s * rs[head];
    }
}

// ---------------------------------------------------------------------------
extern "C" void kernel_launch(void* const* d_in, const int* in_sizes, int n_in,
                              void* d_out, int out_size)
{
    (void)in_sizes; (void)n_in; (void)out_size;
    const float* x    = (const float*)d_in[0];
    const float* pair = (const float*)d_in[1];
    // d_in[2]=rotations, d_in[3]=translations, d_in[4]=mask: unused by reference math
    const float* Wq = (const float*)d_in[5];
    const float* Wk = (const float*)d_in[6];
    const float* Wv = (const float*)d_in[7];
    const float* Wb = (const float*)d_in[8];
    const float* bb = (const float*)d_in[9];
    float* out = (float*)d_out;

    proj_kernel<<<dim3(64, 3, 1), 256>>>(x, Wq, Wk, Wv);

    cudaFuncSetAttribute(fused_kernel, cudaFuncAttributeMaxDynamicSharedMemorySize, SMEM_B);
    fused_kernel<<<1024, 256, SMEM_B>>>(pair, Wb, bb, out);
}

// round 14
// speedup vs baseline: 1.0021x; 1.0021x over previous
#include <cuda_runtime.h>
#include <cstdint>
#include <cstddef>

#define NN   1024
#define DIMX 384
#define HN   8
#define PDW  128
#define OUTW 1152   // H*DV + H*PD = 128 + 1024

static constexpr float SCALAR_SCALE = 0.14433756729740643f; // (3*16)^-0.5
static constexpr float PAIR_SCALE   = 0.5773502691896258f;  // 3^-0.5

// Scratch (static __device__ — no allocations allowed)
static __device__ float g_q[NN * 128];
static __device__ float g_k[NN * 128];
static __device__ float g_v[NN * 128];
static __device__ float g_P[(size_t)NN * NN * 8];      // 32 MB: P = exp(logits), [i][j][h]
static __device__ float g_part[(size_t)NN * 2 * 1184]; // per-(i,half) partials

typedef unsigned long long u64;

__device__ __forceinline__ u64 pack2(float lo, float hi) {
    u64 r; asm("mov.b64 %0, {%1, %2};" : "=l"(r) : "f"(lo), "f"(hi)); return r;
}
__device__ __forceinline__ void unpack2(u64 v, float& lo, float& hi) {
    asm("mov.b64 {%0, %1}, %2;" : "=f"(lo), "=f"(hi) : "l"(v));
}
__device__ __forceinline__ u64 ffma2(u64 a, u64 b, u64 c) {
    u64 r; asm("fma.rn.f32x2 %0, %1, %2, %3;" : "=l"(r) : "l"(a), "l"(b), "l"(c)); return r;
}
__device__ __forceinline__ uint32_t smem_u32(const void* p) {
    return (uint32_t)__cvta_generic_to_shared(p);
}
__device__ __forceinline__ void cp16_cg(uint32_t dst, const void* src) {
    asm volatile("cp.async.cg.shared.global [%0], [%1], 16;" :: "r"(dst), "l"(src));
}
#define CP_COMMIT() asm volatile("cp.async.commit_group;" ::: "memory")
#define CP_WAIT(N)  asm volatile("cp.async.wait_group %0;" :: "n"(N) : "memory")

// qkbias ring: 4 slots x 512B per warp, 16 warps
#define QB_SLOT  512
#define QB_RINGW (4 * QB_SLOT)       // 2 KB / warp
#define QB_SMEM  (16 * QB_RINGW)     // 32 KB

// ---------------------------------------------------------------------------
// Kernel A: q/k/v projections. grid (64, 3), block 256 (8 warps).
// Warp = 8 rows x 32 cols: W slice/warp = 49 KB -> total W L2 traffic 75 MB.
// ---------------------------------------------------------------------------
__global__ void __launch_bounds__(256) proj_kernel(
    const float* __restrict__ x,
    const float* __restrict__ Wq,
    const float* __restrict__ Wk,
    const float* __restrict__ Wv)
{
    __shared__ float xs[16 * DIMX];   // 24 KB
    const int rb = blockIdx.x * 16;
    const float* W   = (blockIdx.y == 0) ? Wq  : (blockIdx.y == 1) ? Wk  : Wv;
    float*       dst = (blockIdx.y == 0) ? g_q : (blockIdx.y == 1) ? g_k : g_v;
    const float scale = (blockIdx.y == 0) ? SCALAR_SCALE : 1.0f;

    for (int t = threadIdx.x; t < 16 * DIMX; t += 256)
        xs[t] = x[(size_t)rb * DIMX + t];
    __syncthreads();

    const int wid  = threadIdx.x >> 5;
    const int lane = threadIdx.x & 31;
    const int rg   = wid >> 2;
    const int cg   = wid & 3;
    const int c    = cg * 32 + lane;
    const int r0   = rg * 8;

    float acc[8];
#pragma unroll
    for (int r = 0; r < 8; r++) acc[r] = 0.0f;

    float wbuf[4];
#pragma unroll
    for (int u = 0; u < 4; u++)
        wbuf[u] = __ldg(&W[u * 128 + c]);

#pragma unroll 1
    for (int k0 = 0; k0 < DIMX; k0 += 4) {
        float wcur[4];
#pragma unroll
        for (int u = 0; u < 4; u++) wcur[u] = wbuf[u];
        const int kn = (k0 + 4 < DIMX) ? (k0 + 4) : 0;   // clamp: valid addr
#pragma unroll
        for (int u = 0; u < 4; u++)
            wbuf[u] = __ldg(&W[(kn + u) * 128 + c]);
#pragma unroll
        for (int u = 0; u < 4; u++) {
#pragma unroll
            for (int r = 0; r < 8; r++)
                acc[r] = fmaf(xs[(r0 + r) * DIMX + k0 + u], wcur[u], acc[r]);
        }
    }
#pragma unroll
    for (int r = 0; r < 8; r++)
        dst[(size_t)(rb + r0 + r) * 128 + c] = acc[r] * scale;
}

// ---------------------------------------------------------------------------
// Kernel B: FUSED qk + bias + exp -> g_P. grid 1024, block 512 (16 warps).
// Warp = 64 consecutive j of one i. Lane = (h = lane&7, q = lane>>3).
// pr staged via cp.async ring (1 LDGSTS/j, ZERO buffer regs); consumed
// directly from smem into the dot (8 LDS.128, 8-way broadcast, conflict-
// free). k via 2-deep __ldg reg buffer. No accumulators -> ~85 regs.
// ---------------------------------------------------------------------------
__global__ void __launch_bounds__(512, 1) qkbias_kernel(
    const float* __restrict__ pair,
    const float* __restrict__ Wb,
    const float* __restrict__ bb)
{
    __shared__ char ring[QB_SMEM];

    const int tid  = threadIdx.x;
    const int wid  = tid >> 5;
    const int lane = tid & 31;
    const int h    = lane & 7;
    const int q    = lane >> 3;

    const int wg = blockIdx.x * 16 + wid;       // 0..16383
    const int i  = wg >> 4;
    const int j0 = (wg & 15) * 64;
    const size_t base0 = (size_t)i * NN + j0;

    // Wb rows for this lane's d-set (chunks f = u*4+q), pre-scaled.
    u64 wb2[16];
#pragma unroll
    for (int u = 0; u < 8; u++) {
        const int d = (u * 4 + q) * 4;
        wb2[2 * u]     = pack2(Wb[(d + 0) * 8 + h] * PAIR_SCALE, Wb[(d + 1) * 8 + h] * PAIR_SCALE);
        wb2[2 * u + 1] = pack2(Wb[(d + 2) * 8 + h] * PAIR_SCALE, Wb[(d + 3) * 8 + h] * PAIR_SCALE);
    }
    const float4 qv = *(const float4*)&g_q[(size_t)i * 128 + h * 16 + q * 4];
    const float bbh = bb[h] * PAIR_SCALE;

    const float4* k4g = (const float4*)g_k;
    const int koff = h * 4 + q;

    const char* prsrc = (const char*)pair + base0 * 512;
    const int lb = lane * 16;
    const uint32_t ringw = smem_u32(ring) + wid * QB_RINGW;
    const char* ringp = ring + wid * QB_RINGW;

    // k 2-deep reg buffer
    float4 kA = __ldg(k4g + (size_t)j0 * 32 + koff);
    float4 kB = __ldg(k4g + (size_t)(j0 + 1) * 32 + koff);

    // prologue: stage pr rows 0,1,2
#pragma unroll
    for (int t = 0; t < 3; t++) {
        cp16_cg(ringw + t * QB_SLOT + lb, prsrc + (size_t)t * 512 + lb);
        CP_COMMIT();
    }

#pragma unroll 1
    for (int t = 0; t < 64; t++) {
        CP_WAIT(2);
        __syncwarp();

        const float4* sp = (const float4*)(ringp + (t & 3) * QB_SLOT);

        u64 a0 = 0ull, a1 = 0ull;
#pragma unroll
        for (int u = 0; u < 8; u++) {
            const float4 c = sp[u * 4 + q];
            a0 = ffma2(pack2(c.x, c.y), wb2[2 * u],     a0);
            a1 = ffma2(pack2(c.z, c.w), wb2[2 * u + 1], a1);
        }

        const float4 kc = (t & 1) ? kB : kA;
        // refill consumed k slot for j = t+2
        const int tk = (t + 2 < 64) ? (t + 2) : (t & 1);   // clamp: valid addr
        if (t & 1) kB = __ldg(k4g + (size_t)(j0 + tk) * 32 + koff);
        else       kA = __ldg(k4g + (size_t)(j0 + tk) * 32 + koff);

        float d0, d1, d2, d3;
        unpack2(a0, d0, d1); unpack2(a1, d2, d3);
        float qk = qv.x * kc.x;
        qk = fmaf(qv.y, kc.y, qk);
        qk = fmaf(qv.z, kc.z, qk);
        qk = fmaf(qv.w, kc.w, qk);

        float dot = ((d0 + d1) + (d2 + d3)) + qk;
        dot += __shfl_xor_sync(0xffffffffu, dot, 8);
        dot += __shfl_xor_sync(0xffffffffu, dot, 16);

        const float p = __expf(dot + bbh);
        if (lane < 8)
            g_P[(base0 + t) * 8 + h] = p;

        __syncwarp();                    // all lanes done with slot before refill

        const int tr = (t + 3) & 63;     // wrapped valid addr
        cp16_cg(ringw + ((t + 3) & 3) * QB_SLOT + lb, prsrc + (size_t)tr * 512 + lb);
        CP_COMMIT();
    }
    CP_WAIT(0);
}

// ---------------------------------------------------------------------------
// Kernel C: dual aggregation (partials). grid 256: CTA -> (i-oct, j-half).
// block 512 (16 warps): warp -> (iw = wid&7, jpar = wid>>3); 256 j's each.
// Lane owns d-slice [lane*4, lane*4+4). 2-deep rolling LDG prefetch (pr, P).
// Writes UNNORMALIZED partials + denom to g_part.   [R7-measured structure]
// ---------------------------------------------------------------------------
__global__ void __launch_bounds__(512, 1) attn_kernel(
    const float* __restrict__ pair)
{
    extern __shared__ float sm[];
    float* vs = sm;                  // 128 x 128 v-chunk (64 KB)
    float* mb = sm + 128 * 128;      // 8 x 1160 merge buffer (37 KB)

    const int tid  = threadIdx.x;
    const int wid  = tid >> 5;
    const int lane = tid & 31;
    const int iw   = wid & 7;
    const int jpar = wid >> 3;
    const int half = blockIdx.x & 1;
    const int i    = (blockIdx.x >> 1) * 8 + iw;
    const int jh0  = half * 512;
    const bool lanehi = (lane >= 16);

    u64 accp[16];
#pragma unroll
    for (int t = 0; t < 16; t++) accp[t] = 0ull;
    float accv[4] = {0.f, 0.f, 0.f, 0.f};
    float4 l03 = make_float4(0.f, 0.f, 0.f, 0.f);
    float4 l47 = make_float4(0.f, 0.f, 0.f, 0.f);

    const float4* gv4 = (const float4*)g_v;
    const float4* gp4 = (const float4*)g_P;
    const float4* pp4 = (const float4*)pair;
    const size_t irow = (size_t)i * NN;
    const int jmax = jh0 + 511;

    float4 prN1, pN1a, pN1b, prN2, pN2a, pN2b;
    {
        const size_t b1 = irow + jh0 + jpar;
        const size_t b2 = b1 + 2;
        prN1 = __ldg(pp4 + b1 * 32 + lane);
        pN1a = __ldg(gp4 + b1 * 2);  pN1b = __ldg(gp4 + b1 * 2 + 1);
        prN2 = __ldg(pp4 + b2 * 32 + lane);
        pN2a = __ldg(gp4 + b2 * 2);  pN2b = __ldg(gp4 + b2 * 2 + 1);
    }

    for (int jc = jh0; jc < jh0 + 512; jc += 128) {
        __syncthreads();
#pragma unroll
        for (int u = 0; u < 8; u++)
            ((float4*)vs)[u * 512 + tid] = gv4[(size_t)jc * 32 + u * 512 + tid];
        __syncthreads();

#pragma unroll 2
        for (int jl = jpar; jl < 128; jl += 2) {
            const float4 pr  = prN1;
            const float4 p03 = pN1a;
            const float4 p47 = pN1b;
            prN1 = prN2; pN1a = pN2a; pN1b = pN2b;

            int jn = jc + jl + 4;
            jn = (jn <= jmax) ? jn : jmax;             // clamp: valid addr
            const size_t bn = irow + jn;
            prN2 = __ldg(pp4 + bn * 32 + lane);
            pN2a = __ldg(gp4 + bn * 2);
            pN2b = __ldg(gp4 + bn * 2 + 1);

            l03.x += p03.x; l03.y += p03.y; l03.z += p03.z; l03.w += p03.w;
            l47.x += p47.x; l47.y += p47.y; l47.z += p47.z; l47.w += p47.w;

            const u64 pr01 = pack2(pr.x, pr.y);
            const u64 pr23 = pack2(pr.z, pr.w);
            const float p[8] = { p03.x, p03.y, p03.z, p03.w, p47.x, p47.y, p47.z, p47.w };

#pragma unroll
            for (int h = 0; h < 8; h++) {
                const u64 ph = pack2(p[h], p[h]);
                accp[2 * h]     = ffma2(ph, pr01, accp[2 * h]);
                accp[2 * h + 1] = ffma2(ph, pr23, accp[2 * h + 1]);
            }

#pragma unroll
            for (int r = 0; r < 4; r++) {
                const float pv = lanehi ? p[2 * r + 1] : p[2 * r];
                accv[r] = fmaf(pv, vs[jl * 128 + r * 32 + lane], accv[r]);
            }
        }
    }

    __syncthreads();

    if (jpar == 1) {
        float* m = mb + iw * 1160;
#pragma unroll
        for (int r = 0; r < 4; r++) m[r * 32 + lane] = accv[r];
#pragma unroll
        for (int h = 0; h < 8; h++) {
            float a0, a1, a2, a3;
            unpack2(accp[2 * h],     a0, a1);
            unpack2(accp[2 * h + 1], a2, a3);
            *(float4*)&m[128 + h * 128 + lane * 4] = make_float4(a0, a1, a2, a3);
        }
        if (lane == 0) {
            *(float4*)&m[1152] = l03;
            *(float4*)&m[1156] = l47;
        }
    }
    __syncthreads();

    if (jpar == 0) {
        const float* m = mb + iw * 1160;
        float* gp = g_part + (size_t)(i * 2 + half) * 1184;

#pragma unroll
        for (int r = 0; r < 4; r++)
            gp[r * 32 + lane] = accv[r] + m[r * 32 + lane];
#pragma unroll
        for (int h = 0; h < 8; h++) {
            float a0, a1, a2, a3;
            unpack2(accp[2 * h],     a0, a1);
            unpack2(accp[2 * h + 1], a2, a3);
            const float4 pm = *(const float4*)&m[128 + h * 128 + lane * 4];
            *(float4*)&gp[128 + h * 128 + lane * 4] = make_float4(
                a0 + pm.x, a1 + pm.y, a2 + pm.z, a3 + pm.w);
        }
        if (lane == 0) {
            const float4 ml03 = *(const float4*)&m[1152];
            const float4 ml47 = *(const float4*)&m[1156];
            *(float4*)&gp[1152] = make_float4(l03.x + ml03.x, l03.y + ml03.y,
                                              l03.z + ml03.z, l03.w + ml03.w);
            *(float4*)&gp[1156] = make_float4(l47.x + ml47.x, l47.y + ml47.y,
                                              l47.z + ml47.z, l47.w + ml47.w);
        }
    }
}

// ---------------------------------------------------------------------------
// Kernel D: merge halves + normalize + store. grid 64, block 512.
// ---------------------------------------------------------------------------
__global__ void __launch_bounds__(512) merge_kernel(float* __restrict__ out)
{
    const int wid  = threadIdx.x >> 5;
    const int lane = threadIdx.x & 31;
    const int i    = blockIdx.x * 16 + wid;
    const bool lanehi = (lane >= 16);

    const float* pa = g_part + (size_t)(i * 2) * 1184;
    const float* pb = pa + 1184;

    float r_own = 0.0f;
    if (lane < 8)
        r_own = 1.0f / (pa[1152 + lane] + pb[1152 + lane]);
    float rinv[8];
#pragma unroll
    for (int h = 0; h < 8; h++)
        rinv[h] = __shfl_sync(0xffffffffu, r_own, h);

    const size_t ob = (size_t)i * OUTW;
#pragma unroll
    for (int r = 0; r < 4; r++) {
        const float s = pa[r * 32 + lane] + pb[r * 32 + lane];
        const float rv = lanehi ? rinv[2 * r + 1] : rinv[2 * r];
        out[ob + r * 32 + lane] = s * rv;
    }
#pragma unroll
    for (int h = 0; h < 8; h++) {
        const float4 a = *(const float4*)&pa[128 + h * 128 + lane * 4];
        const float4 b = *(const float4*)&pb[128 + h * 128 + lane * 4];
        *(float4*)&out[ob + 128 + h * 128 + lane * 4] = make_float4(
            (a.x + b.x) * rinv[h], (a.y + b.y) * rinv[h],
            (a.z + b.z) * rinv[h], (a.w + b.w) * rinv[h]);
    }
}

// ---------------------------------------------------------------------------
extern "C" void kernel_launch(void* const* d_in, const int* in_sizes, int n_in,
                              void* d_out, int out_size)
{
    (void)in_sizes; (void)n_in; (void)out_size;
    const float* x    = (const float*)d_in[0];
    const float* pair = (const float*)d_in[1];
    // d_in[2]=rotations, d_in[3]=translations, d_in[4]=mask: unused by reference math
    const float* Wq = (const float*)d_in[5];
    const float* Wk = (const float*)d_in[6];
    const float* Wv = (const float*)d_in[7];
    const float* Wb = (const float*)d_in[8];
    const float* bb = (const float*)d_in[9];
    float* out = (float*)d_out;

    proj_kernel<<<dim3(64, 3, 1), 256>>>(x, Wq, Wk, Wv);
    qkbias_kernel<<<1024, 512>>>(pair, Wb, bb);

    const int smem = (128 * 128 + 8 * 1160) * (int)sizeof(float); // 102656 B
    cudaFuncSetAttribute(attn_kernel, cudaFuncAttributeMaxDynamicSharedMemorySize, smem);
    attn_kernel<<<256, 512, smem>>>(pair);

    merge_kernel<<<64, 512>>>(out);
}

// round 15
// speedup vs baseline: 1.1147x; 1.1123x over previous
#include <cuda_runtime.h>
#include <cstdint>
#include <cstddef>

#define NN   1024
#define DIMX 384
#define HN   8
#define PDW  128
#define OUTW 1152   // H*DV + H*PD = 128 + 1024

static constexpr float SCALAR_SCALE = 0.14433756729740643f; // (3*16)^-0.5
static constexpr float PAIR_SCALE   = 0.5773502691896258f;  // 3^-0.5

// Scratch (static __device__ — no allocations allowed)
static __device__ float g_q[NN * 128];
static __device__ float g_k[NN * 128];
static __device__ float g_v[NN * 128];

typedef unsigned long long u64;

__device__ __forceinline__ u64 pack2(float lo, float hi) {
    u64 r; asm("mov.b64 %0, {%1, %2};" : "=l"(r) : "f"(lo), "f"(hi)); return r;
}
__device__ __forceinline__ void unpack2(u64 v, float& lo, float& hi) {
    asm("mov.b64 {%0, %1}, %2;" : "=f"(lo), "=f"(hi) : "l"(v));
}
__device__ __forceinline__ u64 ffma2(u64 a, u64 b, u64 c) {
    u64 r; asm("fma.rn.f32x2 %0, %1, %2, %3;" : "=l"(r) : "l"(a), "l"(b), "l"(c)); return r;
}
__device__ __forceinline__ uint32_t smem_u32(const void* p) {
    return (uint32_t)__cvta_generic_to_shared(p);
}
__device__ __forceinline__ void cp16_cg(uint32_t dst, const void* src) {
    asm volatile("cp.async.cg.shared.global [%0], [%1], 16;" :: "r"(dst), "l"(src));
}
#define CP_COMMIT() asm volatile("cp.async.commit_group;" ::: "memory")
#define CP_WAIT(N)  asm volatile("cp.async.wait_group %0;" :: "n"(N) : "memory")

// fused smem layout (bytes): pr ring (8 warps x 4 slots x 512B) + partials
#define FR_SLOT   512
#define FR_RINGW  (4 * FR_SLOT)          // 2 KB / warp
#define FR_RING   (8 * FR_RINGW)         // 16 KB
#define FR_MB     (8 * 1160 * 4)         // 37120 B
#define FR_SMEM   (FR_RING + FR_MB + 64) // 53568 B -> 2 CTAs = 107 KB/SM

// ---------------------------------------------------------------------------
// Kernel A: q/k/v projections. grid (64, 3), block 256 (8 warps).
// Warp = 8 rows x 32 cols: W slice/warp = 49 KB -> total W L2 traffic 75 MB.
// ---------------------------------------------------------------------------
__global__ void __launch_bounds__(256) proj_kernel(
    const float* __restrict__ x,
    const float* __restrict__ Wq,
    const float* __restrict__ Wk,
    const float* __restrict__ Wv)
{
    __shared__ float xs[16 * DIMX];   // 24 KB
    const int rb = blockIdx.x * 16;
    const float* W   = (blockIdx.y == 0) ? Wq  : (blockIdx.y == 1) ? Wk  : Wv;
    float*       dst = (blockIdx.y == 0) ? g_q : (blockIdx.y == 1) ? g_k : g_v;
    const float scale = (blockIdx.y == 0) ? SCALAR_SCALE : 1.0f;

    for (int t = threadIdx.x; t < 16 * DIMX; t += 256)
        xs[t] = x[(size_t)rb * DIMX + t];
    __syncthreads();

    const int wid  = threadIdx.x >> 5;
    const int lane = threadIdx.x & 31;
    const int rg   = wid >> 2;
    const int cg   = wid & 3;
    const int c    = cg * 32 + lane;
    const int r0   = rg * 8;

    float acc[8];
#pragma unroll
    for (int r = 0; r < 8; r++) acc[r] = 0.0f;

    float wbuf[4];
#pragma unroll
    for (int u = 0; u < 4; u++)
        wbuf[u] = __ldg(&W[u * 128 + c]);

#pragma unroll 1
    for (int k0 = 0; k0 < DIMX; k0 += 4) {
        float wcur[4];
#pragma unroll
        for (int u = 0; u < 4; u++) wcur[u] = wbuf[u];
        const int kn = (k0 + 4 < DIMX) ? (k0 + 4) : 0;   // clamp: valid addr
#pragma unroll
        for (int u = 0; u < 4; u++)
            wbuf[u] = __ldg(&W[(kn + u) * 128 + c]);
#pragma unroll
        for (int u = 0; u < 4; u++) {
#pragma unroll
            for (int r = 0; r < 8; r++)
                acc[r] = fmaf(xs[(r0 + r) * DIMX + k0 + u], wcur[u], acc[r]);
        }
    }
#pragma unroll
    for (int r = 0; r < 8; r++)
        dst[(size_t)(rb + r0 + r) * 128 + c] = acc[r] * scale;
}

// ---------------------------------------------------------------------------
// Kernel B: FULLY FUSED single pass (v3). grid 1024 (CTA = query i),
// block 256 (8 warps; warp = 128 consecutive j). 2 CTAs/SM -> 16 warps/SM.
// Lane = (h = lane&7, q = lane>>3).
//
// Per j:
//   pr row staged by 1 cp.async per lane (zero buffer regs, 3 rows in flight)
//   pr chunks f = u*4+q read from smem ONCE into 32 regs (8 LDS.128,
//     4 distinct addrs each, 8-way h-broadcast -> conflict-free), used for
//     BOTH the bias dot and (after exp) the accp accumulation
//   k,v (h,q)-slices via direct __ldg (L1-resident across CTAs)
//   lane-local dot -> xor8/xor16 fold -> exp -> accp/accv/l
// Registers: wb2 32 + accp 32 + pr 32 + qv/accv 8 + transients ~20 = ~124
//   -> fits the 128-reg cap at 2 CTAs/SM with NO re-read and NO spill.
// Epilogue: smem reduce across 8 warps, normalize, direct store.
// ---------------------------------------------------------------------------
__global__ void __launch_bounds__(256, 2) fused_kernel(
    const float* __restrict__ pair,
    const float* __restrict__ Wb,
    const float* __restrict__ bb,
    float* __restrict__ out)
{
    extern __shared__ char smem[];
    float* mb = (float*)(smem + FR_RING);    // 8 x 1160 partials
    float* rs = (float*)(smem + FR_RING + FR_MB);

    const int tid  = threadIdx.x;
    const int wid  = tid >> 5;
    const int lane = tid & 31;
    const int h    = lane & 7;
    const int q    = lane >> 3;

    const int i  = blockIdx.x;
    const int j0 = wid * 128;

    // Wb rows for this lane's d-set (chunks f = u*4+q), pre-scaled.
    u64 wb2[16];
#pragma unroll
    for (int u = 0; u < 8; u++) {
        const int d = (u * 4 + q) * 4;
        wb2[2 * u]     = pack2(Wb[(d + 0) * 8 + h] * PAIR_SCALE, Wb[(d + 1) * 8 + h] * PAIR_SCALE);
        wb2[2 * u + 1] = pack2(Wb[(d + 2) * 8 + h] * PAIR_SCALE, Wb[(d + 3) * 8 + h] * PAIR_SCALE);
    }
    const float4 qv = *(const float4*)&g_q[(size_t)i * 128 + h * 16 + q * 4];
    const float bbh = bb[h] * PAIR_SCALE;
    const int koff = h * 4 + q;      // float4 index of (h,q) slice in a row

    const float4* k4g = (const float4*)g_k;
    const float4* v4g = (const float4*)g_v;

    const char* prsrc = (const char*)pair + ((size_t)i * NN + j0) * 512;
    const int lb = lane * 16;
    const uint32_t ringw = smem_u32(smem) + wid * FR_RINGW;
    const char* ringp = smem + wid * FR_RINGW;

    u64 accp[16];
#pragma unroll
    for (int t = 0; t < 16; t++) accp[t] = 0ull;
    float4 accv = make_float4(0.f, 0.f, 0.f, 0.f);
    float l = 0.0f;

    // prologue: stage pr rows 0,1,2
#pragma unroll
    for (int t = 0; t < 3; t++) {
        cp16_cg(ringw + t * FR_SLOT + lb, prsrc + (size_t)t * 512 + lb);
        CP_COMMIT();
    }

#pragma unroll 1
    for (int t = 0; t < 128; t++) {
        // issue k/v loads first so their latency overlaps the LDS + dot
        const float4 kc = __ldg(k4g + (size_t)(j0 + t) * 32 + koff);
        const float4 vc = __ldg(v4g + (size_t)(j0 + t) * 32 + koff);

        CP_WAIT(2);
        __syncwarp();

        const float4* sp = (const float4*)(ringp + (t & 3) * FR_SLOT);

        // load pr chunks ONCE into registers (used for dot AND accp)
        u64 pr2[16];
#pragma unroll
        for (int u = 0; u < 8; u++) {
            const float4 c = sp[u * 4 + q];
            pr2[2 * u]     = pack2(c.x, c.y);
            pr2[2 * u + 1] = pack2(c.z, c.w);
        }

        // bias dot: two independent f32x2 chains
        u64 a0 = 0ull, a1 = 0ull;
#pragma unroll
        for (int u = 0; u < 8; u++) {
            a0 = ffma2(pr2[2 * u],     wb2[2 * u],     a0);
            a1 = ffma2(pr2[2 * u + 1], wb2[2 * u + 1], a1);
        }
        float d0, d1, d2, d3;
        unpack2(a0, d0, d1); unpack2(a1, d2, d3);

        float qk = qv.x * kc.x;
        qk = fmaf(qv.y, kc.y, qk);
        qk = fmaf(qv.z, kc.z, qk);
        qk = fmaf(qv.w, kc.w, qk);

        float dot = ((d0 + d1) + (d2 + d3)) + qk;
        dot += __shfl_xor_sync(0xffffffffu, dot, 8);
        dot += __shfl_xor_sync(0xffffffffu, dot, 16);

        const float p = __expf(dot + bbh);       // same on all 4 q-lanes of h
        l += p;
        const u64 ph = pack2(p, p);

#pragma unroll
        for (int u = 0; u < 16; u++) accp[u] = ffma2(ph, pr2[u], accp[u]);

        accv.x = fmaf(p, vc.x, accv.x);
        accv.y = fmaf(p, vc.y, accv.y);
        accv.z = fmaf(p, vc.z, accv.z);
        accv.w = fmaf(p, vc.w, accv.w);

        __syncwarp();                    // all lanes done reading slot

        // refill slot (t+3)&3 with row (t+3) (wrapped valid addr)
        const int tr = (t + 3) & 127;
        cp16_cg(ringw + ((t + 3) & 3) * FR_SLOT + lb, prsrc + (size_t)tr * 512 + lb);
        CP_COMMIT();
    }
    CP_WAIT(0);

    // ---- epilogue: dump per-warp partials, reduce across 8 warps ----
    {
        float* m = mb + wid * 1160;
        *(float4*)&m[koff * 4] = accv;                    // v part: h*16 + q*4
#pragma unroll
        for (int u = 0; u < 8; u++) {
            float a0, a1, a2, a3;
            unpack2(accp[2 * u],     a0, a1);
            unpack2(accp[2 * u + 1], a2, a3);
            *(float4*)&m[128 + h * 128 + u * 16 + q * 4] = make_float4(a0, a1, a2, a3);
        }
        if (q == 0) m[1152 + h] = l;
    }
    __syncthreads();

    if (tid < 8) {
        float s = 0.0f;
#pragma unroll
        for (int w = 0; w < 8; w++) s += mb[w * 1160 + 1152 + tid];
        rs[tid] = 1.0f / s;
    }
    __syncthreads();

    const size_t ob = (size_t)i * OUTW;
    for (int idx = tid; idx < OUTW; idx += 256) {
        float s = 0.0f;
#pragma unroll
        for (int w = 0; w < 8; w++) s += mb[w * 1160 + idx];
        const int head = (idx < 128) ? (idx >> 4) : ((idx - 128) >> 7);
        out[ob + idx] = s * rs[head];
    }
}

// ---------------------------------------------------------------------------
extern "C" void kernel_launch(void* const* d_in, const int* in_sizes, int n_in,
                              void* d_out, int out_size)
{
    (void)in_sizes; (void)n_in; (void)out_size;
    const float* x    = (const float*)d_in[0];
    const float* pair = (const float*)d_in[1];
    // d_in[2]=rotations, d_in[3]=translations, d_in[4]=mask: unused by reference math
    const float* Wq = (const float*)d_in[5];
    const float* Wk = (const float*)d_in[6];
    const float* Wv = (const float*)d_in[7];
    const float* Wb = (const float*)d_in[8];
    const float* bb = (const float*)d_in[9];
    float* out = (float*)d_out;

    proj_kernel<<<dim3(64, 3, 1), 256>>>(x, Wq, Wk, Wv);

    cudaFuncSetAttribute(fused_kernel, cudaFuncAttributeMaxDynamicSharedMemorySize, FR_SMEM);
    fused_kernel<<<1024, 256, FR_SMEM>>>(pair, Wb, bb, out);
}